// round 12
// baseline (speedup 1.0000x reference)
#include <cuda_runtime.h>
#include <cuda_bf16.h>
#include <math_constants.h>
#include <cstdint>

#define Bq  4
#define Tt  2048
#define Dd  2048
#define Hh  16
#define DHd 128
#define Mm  (Bq * Tt)        // 8192
#define SCALE 0.08838834764831845f  // DH^-0.5

// ---------------------------------------------------------------------------
// Persistent bf16 hi/lo tensors (allocation-free rule: __device__ globals)
// ---------------------------------------------------------------------------
__device__ __align__(256) __nv_bfloat16 g_xh[Mm * Dd];
__device__ __align__(256) __nv_bfloat16 g_xl[Mm * Dd];
__device__ __align__(256) __nv_bfloat16 g_wth[4][Dd * Dd];   // W^T hi, [N][K]
__device__ __align__(256) __nv_bfloat16 g_wtl[4][Dd * Dd];   // W^T lo
__device__ __align__(256) __nv_bfloat16 g_qh[Bq * Hh * Tt * DHd];
__device__ __align__(256) __nv_bfloat16 g_ql[Bq * Hh * Tt * DHd];
__device__ __align__(256) __nv_bfloat16 g_kh[Bq * Hh * Tt * DHd];
__device__ __align__(256) __nv_bfloat16 g_kl[Bq * Hh * Tt * DHd];
__device__ __align__(256) __nv_bfloat16 g_vth[Bq * Hh * DHd * Tt];  // [b,h,d,t]
__device__ __align__(256) __nv_bfloat16 g_vtl[Bq * Hh * DHd * Tt];
__device__ __align__(256) __nv_bfloat16 g_atth[Bq * Tt * Dd];
__device__ __align__(256) __nv_bfloat16 g_attl[Bq * Tt * Dd];

// ===========================================================================
// Helpers
// ===========================================================================
__device__ __forceinline__ uint32_t smem_u32(const void* p) {
    uint32_t a;
    asm("{ .reg .u64 t; cvta.to.shared.u64 t, %1; cvt.u32.u64 %0, t; }" : "=r"(a) : "l"(p));
    return a;
}
__device__ __forceinline__ void cp16(uint32_t dst, const void* src) {
    asm volatile("cp.async.cg.shared.global [%0], [%1], 16;" :: "r"(dst), "l"(src));
}
#define CP_COMMIT() asm volatile("cp.async.commit_group;" ::: "memory")
#define CP_WAIT0()  asm volatile("cp.async.wait_group 0;" ::: "memory")
#define CP_WAIT2()  asm volatile("cp.async.wait_group 2;" ::: "memory")

__device__ __forceinline__ void mma_bf16(float* c, const uint32_t* a,
                                         uint32_t b0, uint32_t b1) {
    asm volatile(
        "mma.sync.aligned.m16n8k16.row.col.f32.bf16.bf16.f32 "
        "{%0,%1,%2,%3}, {%4,%5,%6,%7}, {%8,%9}, {%0,%1,%2,%3};"
        : "+f"(c[0]), "+f"(c[1]), "+f"(c[2]), "+f"(c[3])
        : "r"(a[0]), "r"(a[1]), "r"(a[2]), "r"(a[3]), "r"(b0), "r"(b1));
}
__device__ __forceinline__ void ldsm_x4(uint32_t* r, uint32_t addr) {
    asm volatile("ldmatrix.sync.aligned.m8n8.x4.shared.b16 {%0,%1,%2,%3}, [%4];"
        : "=r"(r[0]), "=r"(r[1]), "=r"(r[2]), "=r"(r[3]) : "r"(addr));
}
__device__ __forceinline__ uint32_t pack_bf16(float v0, float v1) {
    uint32_t h;
    asm("cvt.rn.bf16x2.f32 %0, %1, %2;" : "=r"(h) : "f"(v1), "f"(v0));
    return h;
}
// Split pair of fp32 into bf16x2 hi + bf16x2 residual (lower 16 bits = v0)
__device__ __forceinline__ void bf16_split2(float v0, float v1,
                                            uint32_t& hi, uint32_t& lo) {
    uint32_t h = pack_bf16(v0, v1);
    float f0 = __uint_as_float(h << 16);
    float f1 = __uint_as_float(h & 0xffff0000u);
    lo = pack_bf16(v0 - f0, v1 - f1);
    hi = h;
}

// ===========================================================================
// Conversion kernels
// ===========================================================================
__global__ __launch_bounds__(256)
void conv_x_kernel(const float* __restrict__ src,
                   __nv_bfloat16* __restrict__ hi, __nv_bfloat16* __restrict__ lo)
{
    const size_t i4 = ((size_t)blockIdx.x * 256 + threadIdx.x) * 4;
    float4 v = *(const float4*)(src + i4);
    uint32_t h0, l0, h1, l1;
    bf16_split2(v.x, v.y, h0, l0);
    bf16_split2(v.z, v.w, h1, l1);
    *(uint2*)(hi + i4) = make_uint2(h0, h1);
    *(uint2*)(lo + i4) = make_uint2(l0, l1);
}

// Transpose all 4 W [K][N] -> W^T [N][K], split to bf16 hi/lo. gridDim.z = 4.
__global__ __launch_bounds__(256)
void conv_w_all(const float* __restrict__ W0, const float* __restrict__ W1,
                const float* __restrict__ W2, const float* __restrict__ W3,
                __nv_bfloat16* __restrict__ Th, __nv_bfloat16* __restrict__ Tl)
{
    const int z = blockIdx.z;
    const float* W = (z == 0) ? W0 : (z == 1) ? W1 : (z == 2) ? W2 : W3;
    __nv_bfloat16* th = Th + (size_t)z * Dd * Dd;
    __nv_bfloat16* tl = Tl + (size_t)z * Dd * Dd;

    __shared__ float tile[32][33];
    int x = blockIdx.x * 32 + threadIdx.x;
    int y = blockIdx.y * 32 + threadIdx.y;
#pragma unroll
    for (int j = 0; j < 32; j += 8)
        tile[threadIdx.y + j][threadIdx.x] = W[(size_t)(y + j) * Dd + x];
    __syncthreads();
    int n = blockIdx.x * 32 + threadIdx.y;
    int k = blockIdx.y * 32 + threadIdx.x;
#pragma unroll
    for (int j = 0; j < 32; j += 8) {
        float v = tile[threadIdx.x][threadIdx.y + j];
        __nv_bfloat16 h = __float2bfloat16(v);
        __nv_bfloat16 l = __float2bfloat16(v - __bfloat162float(h));
        th[(size_t)(n + j) * Dd + k] = h;
        tl[(size_t)(n + j) * Dd + k] = l;
    }
}

// ===========================================================================
// bf16 hi/lo tensor-core GEMM core. BM=128, BN=256, BK=32, 8 warps (2x4),
// warp tile 64x64 (128 acc regs). 4-stage cp.async ring (192KB), 1 CTA/SM.
// Dense 64B rows + 16B-chunk XOR swizzle; all fragments via ldmatrix x4.
// ===========================================================================
#define GBM 128
#define GBN 256
#define GBK 32
#define ATILEB 8192                   // 128 rows * 64B
#define BTILEB 16384                  // 256 rows * 64B
#define STAGEB (2 * ATILEB + 2 * BTILEB)   // 49152: Ah|Al|Bh|Bl
#define OFF_AL ATILEB
#define OFF_BH (2 * ATILEB)
#define OFF_BL (2 * ATILEB + BTILEB)
#define GEMM_SMEM (4 * STAGEB)        // 196608 -> 1 CTA/SM

__device__ __forceinline__ void load_stage(uint32_t sdst,
        const __nv_bfloat16* __restrict__ Ah, const __nv_bfloat16* __restrict__ Al,
        const __nv_bfloat16* __restrict__ Bh, const __nv_bfloat16* __restrict__ Bl,
        int m0, int n0, int k0)
{
    const int tid = threadIdx.x;
    // A: 128 rows x 4 chunks = 512 chunks (hi + lo)
#pragma unroll
    for (int l = 0; l < 2; l++) {
        int e = tid + 256 * l;
        int r = e >> 2, c = e & 3;
        int cp_ = c ^ ((r >> 1) & 3);
        uint32_t doff = (uint32_t)(r * 64 + cp_ * 16);
        size_t soff = (size_t)(m0 + r) * Dd + k0 + c * 8;
        cp16(sdst + doff, Ah + soff);
        cp16(sdst + OFF_AL + doff, Al + soff);
    }
    // B: 256 rows x 4 chunks = 1024 chunks (hi + lo)
#pragma unroll
    for (int l = 0; l < 4; l++) {
        int e = tid + 256 * l;
        int r = e >> 2, c = e & 3;
        int cp_ = c ^ ((r >> 1) & 3);
        uint32_t doff = (uint32_t)(r * 64 + cp_ * 16);
        size_t soff = (size_t)(n0 + r) * Dd + k0 + c * 8;
        cp16(sdst + OFF_BH + doff, Bh + soff);
        cp16(sdst + OFF_BL + doff, Bl + soff);
    }
}

__device__ __forceinline__ void gemm_mainloop(
        uint32_t sbase,
        const __nv_bfloat16* __restrict__ Ah, const __nv_bfloat16* __restrict__ Al,
        const __nv_bfloat16* __restrict__ Bth, const __nv_bfloat16* __restrict__ Btl,
        int m0, int n0, float acc[4][8][4])
{
    const int lane = threadIdx.x & 31;
    const int wid  = threadIdx.x >> 5;
    const int wm = wid >> 2, wn = wid & 3;
    const int lr = lane & 7, g = lane >> 3;
    const int swz = (lr >> 1) & 3;
    const uint32_t arow = (uint32_t)((wm * 64 + (g & 1) * 8 + lr) * 64);
    const int akh = g >> 1;
    const uint32_t brow = (uint32_t)((wn * 64 + (g >> 1) * 8 + lr) * 64);
    const int bkh = g & 1;

    load_stage(sbase, Ah, Al, Bth, Btl, m0, n0, 0);
    CP_COMMIT();
    load_stage(sbase + STAGEB, Ah, Al, Bth, Btl, m0, n0, GBK);
    CP_COMMIT();
    load_stage(sbase + 2 * STAGEB, Ah, Al, Bth, Btl, m0, n0, 2 * GBK);
    CP_COMMIT();

    const int NITER = Dd / GBK;   // 64
    int cur = 0;
    for (int it = 0; it < NITER; it++) {
        CP_WAIT2();
        __syncthreads();
        const uint32_t Sb = sbase + (uint32_t)cur * STAGEB;
        if (it + 3 < NITER) {
            int pf = cur + 3; if (pf >= 4) pf -= 4;
            load_stage(sbase + (uint32_t)pf * STAGEB, Ah, Al, Bth, Btl,
                       m0, n0, (it + 3) * GBK);
            CP_COMMIT();
        }
#pragma unroll
        for (int ks = 0; ks < 2; ks++) {
            const uint32_t ca = (uint32_t)(((ks * 2 + akh) ^ swz) * 16);
            const uint32_t cb = (uint32_t)(((ks * 2 + bkh) ^ swz) * 16);
            uint32_t ah[4][4], al[4][4];
#pragma unroll
            for (int i = 0; i < 4; i++) {
                ldsm_x4(ah[i], Sb + arow + (uint32_t)(i * 1024) + ca);
                ldsm_x4(al[i], Sb + OFF_AL + arow + (uint32_t)(i * 1024) + ca);
            }
#pragma unroll
            for (int jj = 0; jj < 4; jj++) {
                uint32_t bh4[4], bl4[4];
                ldsm_x4(bh4, Sb + OFF_BH + brow + (uint32_t)(jj * 1024) + cb);
                ldsm_x4(bl4, Sb + OFF_BL + brow + (uint32_t)(jj * 1024) + cb);
#pragma unroll
                for (int i = 0; i < 4; i++) {
                    mma_bf16(acc[i][2 * jj], ah[i], bh4[0], bh4[1]);
                    mma_bf16(acc[i][2 * jj], al[i], bh4[0], bh4[1]);
                    mma_bf16(acc[i][2 * jj], ah[i], bl4[0], bl4[1]);
                    mma_bf16(acc[i][2 * jj + 1], ah[i], bh4[2], bh4[3]);
                    mma_bf16(acc[i][2 * jj + 1], al[i], bh4[2], bh4[3]);
                    mma_bf16(acc[i][2 * jj + 1], ah[i], bl4[2], bl4[3]);
                }
            }
        }
        cur++; if (cur >= 4) cur = 0;
    }
}

// Fused QKV projection: gridDim.z selects q/k/v weight + epilogue.
__global__ __launch_bounds__(256, 1)
void gemm_qkv(const __nv_bfloat16* __restrict__ xh, const __nv_bfloat16* __restrict__ xl,
              const __nv_bfloat16* __restrict__ wth, const __nv_bfloat16* __restrict__ wtl,
              const float* __restrict__ bq, const float* __restrict__ bk,
              const float* __restrict__ bv)
{
    extern __shared__ char smem[];
    const uint32_t sbase = smem_u32(smem);
    const int z = blockIdx.z;
    const __nv_bfloat16* Bth = wth + (size_t)z * Dd * Dd;
    const __nv_bfloat16* Btl = wtl + (size_t)z * Dd * Dd;
    const float* bias = (z == 0) ? bq : (z == 1) ? bk : bv;
    const int m0 = blockIdx.y * GBM;
    const int n0 = blockIdx.x * GBN;

    float acc[4][8][4];
#pragma unroll
    for (int i = 0; i < 4; i++)
#pragma unroll
        for (int j = 0; j < 8; j++)
#pragma unroll
            for (int r = 0; r < 4; r++) acc[i][j][r] = 0.f;

    gemm_mainloop(sbase, xh, xl, Bth, Btl, m0, n0, acc);

    const int lane = threadIdx.x & 31;
    const int wid  = threadIdx.x >> 5;
    const int q4 = lane & 3, g8 = lane >> 2;
    const int wm = wid >> 2, wn = wid & 3;
    const int mbase = m0 + wm * 64;
#pragma unroll
    for (int j = 0; j < 8; j++) {
        const int nc = wn * 64 + j * 8 + 2 * q4;
        const float bx = bias[n0 + nc];
        const float by = bias[n0 + nc + 1];
#pragma unroll
        for (int i = 0; i < 4; i++) {
#pragma unroll
            for (int half = 0; half < 2; half++) {
                const int m = mbase + i * 16 + g8 + half * 8;
                float vx = acc[i][j][half * 2]     + bx;
                float vy = acc[i][j][half * 2 + 1] + by;
                const int h = (n0 + nc) >> 7;               // BN=256 spans 2 heads
                const int d = (n0 + nc) & 127;
                const int b = m >> 11;
                const int t = m & 2047;
                if (z == 2) {
                    size_t base = ((size_t)(b * Hh + h) * DHd + d) * Tt + t;
                    __nv_bfloat16 h0 = __float2bfloat16(vx);
                    __nv_bfloat16 h1 = __float2bfloat16(vy);
                    g_vth[base]       = h0;
                    g_vth[base + Tt]  = h1;
                    g_vtl[base]       = __float2bfloat16(vx - __bfloat162float(h0));
                    g_vtl[base + Tt]  = __float2bfloat16(vy - __bfloat162float(h1));
                } else {
                    __nv_bfloat16* dh = (z == 0) ? g_qh : g_kh;
                    __nv_bfloat16* dl = (z == 0) ? g_ql : g_kl;
                    size_t base = ((size_t)((b * Hh + h) * Tt) + t) * DHd + d;
                    uint32_t hh, ll;
                    bf16_split2(vx, vy, hh, ll);
                    *(uint32_t*)(dh + base) = hh;
                    *(uint32_t*)(dl + base) = ll;
                }
            }
        }
    }
}

// Output projection: fp32 row-major result.
__global__ __launch_bounds__(256, 1)
void gemm_out(const __nv_bfloat16* __restrict__ Ah, const __nv_bfloat16* __restrict__ Al,
              const __nv_bfloat16* __restrict__ Bth, const __nv_bfloat16* __restrict__ Btl,
              const float* __restrict__ bias, float* __restrict__ Cout)
{
    extern __shared__ char smem[];
    const uint32_t sbase = smem_u32(smem);
    const int m0 = blockIdx.y * GBM;
    const int n0 = blockIdx.x * GBN;

    float acc[4][8][4];
#pragma unroll
    for (int i = 0; i < 4; i++)
#pragma unroll
        for (int j = 0; j < 8; j++)
#pragma unroll
            for (int r = 0; r < 4; r++) acc[i][j][r] = 0.f;

    gemm_mainloop(sbase, Ah, Al, Bth, Btl, m0, n0, acc);

    const int lane = threadIdx.x & 31;
    const int wid  = threadIdx.x >> 5;
    const int q4 = lane & 3, g8 = lane >> 2;
    const int wm = wid >> 2, wn = wid & 3;
    const int mbase = m0 + wm * 64;
#pragma unroll
    for (int j = 0; j < 8; j++) {
        const int nc = wn * 64 + j * 8 + 2 * q4;
        const float bx = bias[n0 + nc];
        const float by = bias[n0 + nc + 1];
#pragma unroll
        for (int i = 0; i < 4; i++) {
#pragma unroll
            for (int half = 0; half < 2; half++) {
                const int m = mbase + i * 16 + g8 + half * 8;
                *(float2*)(Cout + (size_t)m * Dd + n0 + nc) =
                    make_float2(acc[i][j][half * 2] + bx, acc[i][j][half * 2 + 1] + by);
            }
        }
    }
}

// ===========================================================================
// Flash attention (causal), bf16 hi/lo, 3-pass MMA, online softmax.
// BM=128 (8 warps x 16 rows), BN=64, DH=128, 256 threads. (unchanged R11)
// ===========================================================================
#define FBM 128
#define FBN 64
#define QP32 68     // u32 pitch (136 bf16, 272B)
#define KP32 68
#define VP32 36     // 72 bf16, 144B
#define PP32 36
#define F_QH   0u
#define F_QL   34816u
#define F_KH   69632u
#define F_KL   87040u
#define F_V0H  104448u
#define F_VLO  18432u      // lo offset within a V buffer
#define F_VSTR 36864u      // stride between V buffers
#define F_PH   178176u
#define F_PL   196608u
#define FLASH_SMEM 215040

__device__ __forceinline__ void flash_load_q(uint32_t sb,
        const __nv_bfloat16* __restrict__ qh, const __nv_bfloat16* __restrict__ ql) {
    const int tid = threadIdx.x;
#pragma unroll
    for (int l = 0; l < 8; l++) {
        int e = tid + l * 256;
        int r = e >> 4, c = e & 15;
        uint32_t doff = (uint32_t)(r * 272 + c * 16);
        cp16(sb + F_QH + doff, qh + r * 128 + c * 8);
        cp16(sb + F_QL + doff, ql + r * 128 + c * 8);
    }
}
__device__ __forceinline__ void flash_load_k(uint32_t sb,
        const __nv_bfloat16* __restrict__ kh, const __nv_bfloat16* __restrict__ kl) {
    const int tid = threadIdx.x;
#pragma unroll
    for (int l = 0; l < 4; l++) {
        int e = tid + l * 256;
        int r = e >> 4, c = e & 15;
        uint32_t doff = (uint32_t)(r * 272 + c * 16);
        cp16(sb + F_KH + doff, kh + r * 128 + c * 8);
        cp16(sb + F_KL + doff, kl + r * 128 + c * 8);
    }
}
__device__ __forceinline__ void flash_load_v(uint32_t dsth,
        const __nv_bfloat16* __restrict__ vh, const __nv_bfloat16* __restrict__ vl) {
    const int tid = threadIdx.x;
#pragma unroll
    for (int l = 0; l < 4; l++) {
        int e = tid + l * 256;
        int r = e >> 3, c = e & 7;
        uint32_t doff = (uint32_t)(r * 144 + c * 16);
        cp16(dsth + doff, vh + (size_t)r * Tt + c * 8);
        cp16(dsth + F_VLO + doff, vl + (size_t)r * Tt + c * 8);
    }
}

__global__ __launch_bounds__(256, 1)
void flash_tc()
{
    extern __shared__ char smc[];
    const uint32_t sb = smem_u32(smc);
    const int qb = (gridDim.x - 1) - blockIdx.x;    // longest-job-first
    const int h  = blockIdx.y;
    const int b  = blockIdx.z;
    const int q0 = qb * FBM;
    const int tid  = threadIdx.x;
    const int w    = tid >> 5;
    const int lane = tid & 31;
    const int q4   = lane & 3;
    const int rl   = lane >> 2;
    const int lr   = lane & 7;
    const int g    = lane >> 3;

    uint32_t* Ph32 = (uint32_t*)(smc + F_PH);
    uint32_t* Pl32 = (uint32_t*)(smc + F_PL);

    const uint32_t qAddr = sb + F_QH + (uint32_t)((w * 16 + (g & 1) * 8 + lr) * 272 + (g >> 1) * 16);
    const uint32_t kAddr = sb + F_KH + (uint32_t)(((g >> 1) * 8 + lr) * 272 + (g & 1) * 16);
    const uint32_t pAddr = sb + F_PH + (uint32_t)((w * 16 + (g & 1) * 8 + lr) * 144 + (g >> 1) * 16);
    const uint32_t vAddrOff = (uint32_t)(((g >> 1) * 8 + lr) * 144 + (g & 1) * 16);

    const size_t bh = (size_t)(b * Hh + h) * Tt;
    const __nv_bfloat16* kbh = g_kh + bh * DHd;
    const __nv_bfloat16* kbl = g_kl + bh * DHd;
    const __nv_bfloat16* vbh = g_vth + (size_t)(b * Hh + h) * DHd * Tt;
    const __nv_bfloat16* vbl = g_vtl + (size_t)(b * Hh + h) * DHd * Tt;

    flash_load_q(sb, g_qh + (bh + q0) * DHd, g_ql + (bh + q0) * DHd);
    flash_load_k(sb, kbh, kbl);
    flash_load_v(sb + F_V0H, vbh, vbl);
    CP_COMMIT();

    float m_lo = -1e30f, m_hi = -1e30f, l_lo = 0.f, l_hi = 0.f;
    float o[16][4];
#pragma unroll
    for (int nt = 0; nt < 16; nt++)
#pragma unroll
        for (int r = 0; r < 4; r++) o[nt][r] = 0.f;

    const int rowbase = q0 + w * 16;
    const int nkt = 2 * qb + 2;

    for (int t = 0; t < nkt; t++) {
        const int k0 = t * FBN;
        const bool active = (k0 <= rowbase + 15);
        CP_WAIT0();
        __syncthreads();

        if (t + 1 < nkt) {
            flash_load_v(sb + F_V0H + (uint32_t)((t + 1) & 1) * F_VSTR,
                         vbh + (size_t)(t + 1) * FBN, vbl + (size_t)(t + 1) * FBN);
            CP_COMMIT();
        }

        float sacc[8][4];
        if (active) {
#pragma unroll
            for (int j = 0; j < 8; j++)
#pragma unroll
                for (int r = 0; r < 4; r++) sacc[j][r] = 0.f;

#pragma unroll
            for (int ks = 0; ks < 8; ks++) {
                uint32_t ah[4], al[4];
                ldsm_x4(ah, qAddr + (uint32_t)(ks * 32));
                ldsm_x4(al, qAddr + (F_QL - F_QH) + (uint32_t)(ks * 32));
#pragma unroll
                for (int jj = 0; jj < 4; jj++) {
                    uint32_t bh4[4], bl4[4];
                    ldsm_x4(bh4, kAddr + (uint32_t)(jj * 16 * 272 + ks * 32));
                    ldsm_x4(bl4, kAddr + (F_KL - F_KH) + (uint32_t)(jj * 16 * 272 + ks * 32));
                    mma_bf16(sacc[2 * jj], ah, bh4[0], bh4[1]);
                    mma_bf16(sacc[2 * jj], al, bh4[0], bh4[1]);
                    mma_bf16(sacc[2 * jj], ah, bl4[0], bl4[1]);
                    mma_bf16(sacc[2 * jj + 1], ah, bh4[2], bh4[3]);
                    mma_bf16(sacc[2 * jj + 1], al, bh4[2], bh4[3]);
                    mma_bf16(sacc[2 * jj + 1], ah, bl4[2], bl4[3]);
                }
            }
        }

        __syncthreads();
        if (t + 1 < nkt) {
            flash_load_k(sb, kbh + (size_t)(t + 1) * FBN * DHd,
                         kbl + (size_t)(t + 1) * FBN * DHd);
            CP_COMMIT();
        }

        if (active) {
            const int R_lo = rowbase + rl;
            const int R_hi = R_lo + 8;
            const bool needmask = (k0 + FBN - 1) > rowbase;
            float tl = -1e30f, th = -1e30f;
#pragma unroll
            for (int j = 0; j < 8; j++) {
#pragma unroll
                for (int r = 0; r < 4; r++) sacc[j][r] *= SCALE;
                if (needmask) {
                    const int C = k0 + j * 8 + 2 * q4;
                    if (C > R_lo)     sacc[j][0] = -1e30f;
                    if (C + 1 > R_lo) sacc[j][1] = -1e30f;
                    if (C > R_hi)     sacc[j][2] = -1e30f;
                    if (C + 1 > R_hi) sacc[j][3] = -1e30f;
                }
                tl = fmaxf(tl, fmaxf(sacc[j][0], sacc[j][1]));
                th = fmaxf(th, fmaxf(sacc[j][2], sacc[j][3]));
            }
            tl = fmaxf(tl, __shfl_xor_sync(0xffffffffu, tl, 1));
            tl = fmaxf(tl, __shfl_xor_sync(0xffffffffu, tl, 2));
            th = fmaxf(th, __shfl_xor_sync(0xffffffffu, th, 1));
            th = fmaxf(th, __shfl_xor_sync(0xffffffffu, th, 2));

            const float mn_lo = fmaxf(m_lo, tl);
            const float mn_hi = fmaxf(m_hi, th);
            const float a_lo = __expf(m_lo - mn_lo);
            const float a_hi = __expf(m_hi - mn_hi);
            m_lo = mn_lo; m_hi = mn_hi;

            float sum_lo = 0.f, sum_hi = 0.f;
            uint32_t* prl_h = Ph32 + (w * 16 + rl) * PP32;
            uint32_t* prl_l = Pl32 + (w * 16 + rl) * PP32;
#pragma unroll
            for (int j = 0; j < 8; j++) {
                float p0 = __expf(sacc[j][0] - mn_lo);
                float p1 = __expf(sacc[j][1] - mn_lo);
                float p2 = __expf(sacc[j][2] - mn_hi);
                float p3 = __expf(sacc[j][3] - mn_hi);
                sum_lo += p0 + p1;
                sum_hi += p2 + p3;
                uint32_t hh, ll;
                bf16_split2(p0, p1, hh, ll);
                prl_h[j * 4 + q4] = hh;
                prl_l[j * 4 + q4] = ll;
                bf16_split2(p2, p3, hh, ll);
                prl_h[8 * PP32 + j * 4 + q4] = hh;
                prl_l[8 * PP32 + j * 4 + q4] = ll;
            }
            sum_lo += __shfl_xor_sync(0xffffffffu, sum_lo, 1);
            sum_lo += __shfl_xor_sync(0xffffffffu, sum_lo, 2);
            sum_hi += __shfl_xor_sync(0xffffffffu, sum_hi, 1);
            sum_hi += __shfl_xor_sync(0xffffffffu, sum_hi, 2);
            l_lo = l_lo * a_lo + sum_lo;
            l_hi = l_hi * a_hi + sum_hi;

#pragma unroll
            for (int nt = 0; nt < 16; nt++) {
                o[nt][0] *= a_lo; o[nt][1] *= a_lo;
                o[nt][2] *= a_hi; o[nt][3] *= a_hi;
            }
            __syncwarp();

            const uint32_t vAddr = sb + F_V0H + (uint32_t)(t & 1) * F_VSTR + vAddrOff;
#pragma unroll
            for (int ks = 0; ks < 4; ks++) {
                uint32_t ph4[4], pl4[4];
                ldsm_x4(ph4, pAddr + (uint32_t)(ks * 32));
                ldsm_x4(pl4, pAddr + (F_PL - F_PH) + (uint32_t)(ks * 32));
#pragma unroll
                for (int ntp = 0; ntp < 8; ntp++) {
                    uint32_t vh4[4], vl4[4];
                    ldsm_x4(vh4, vAddr + (uint32_t)(ntp * 16 * 144 + ks * 32));
                    ldsm_x4(vl4, vAddr + F_VLO + (uint32_t)(ntp * 16 * 144 + ks * 32));
                    mma_bf16(o[2 * ntp], ph4, vh4[0], vh4[1]);
                    mma_bf16(o[2 * ntp], pl4, vh4[0], vh4[1]);
                    mma_bf16(o[2 * ntp], ph4, vl4[0], vl4[1]);
                    mma_bf16(o[2 * ntp + 1], ph4, vh4[2], vh4[3]);
                    mma_bf16(o[2 * ntp + 1], pl4, vh4[2], vh4[3]);
                    mma_bf16(o[2 * ntp + 1], ph4, vl4[2], vl4[3]);
                }
            }
        }
    }

    const float il_lo = 1.f / l_lo;
    const float il_hi = 1.f / l_hi;
    __nv_bfloat16* oh = g_atth + ((size_t)(b * Tt + rowbase)) * Dd + h * DHd;
    __nv_bfloat16* ol = g_attl + ((size_t)(b * Tt + rowbase)) * Dd + h * DHd;
#pragma unroll
    for (int nt = 0; nt < 16; nt++) {
        uint32_t hh, ll;
        size_t idx0 = (size_t)rl * Dd + nt * 8 + 2 * q4;
        bf16_split2(o[nt][0] * il_lo, o[nt][1] * il_lo, hh, ll);
        *(uint32_t*)(oh + idx0) = hh;
        *(uint32_t*)(ol + idx0) = ll;
        size_t idx1 = (size_t)(rl + 8) * Dd + nt * 8 + 2 * q4;
        bf16_split2(o[nt][2] * il_hi, o[nt][3] * il_hi, hh, ll);
        *(uint32_t*)(oh + idx1) = hh;
        *(uint32_t*)(ol + idx1) = ll;
    }
}

// ===========================================================================
extern "C" void kernel_launch(void* const* d_in, const int* in_sizes, int n_in,
                              void* d_out, int out_size)
{
    const float* x  = (const float*)d_in[0];
    const float* Wq = (const float*)d_in[1];
    const float* bq = (const float*)d_in[2];
    const float* Wk = (const float*)d_in[3];
    const float* bk = (const float*)d_in[4];
    const float* Wv = (const float*)d_in[5];
    const float* bv = (const float*)d_in[6];
    const float* Wo = (const float*)d_in[7];
    const float* bo = (const float*)d_in[8];
    float* out = (float*)d_out;

    __nv_bfloat16 *xh, *xl, *wth, *wtl, *atth, *attl;
    cudaGetSymbolAddress((void**)&xh,   g_xh);
    cudaGetSymbolAddress((void**)&xl,   g_xl);
    cudaGetSymbolAddress((void**)&wth,  g_wth);
    cudaGetSymbolAddress((void**)&wtl,  g_wtl);
    cudaGetSymbolAddress((void**)&atth, g_atth);
    cudaGetSymbolAddress((void**)&attl, g_attl);

    // 1) Convert inputs to bf16 hi/lo (x natural, all 4 W transposed, fused)
    conv_x_kernel<<<(Mm * Dd) / 1024, 256>>>(x, xh, xl);
    dim3 wgrid(Dd / 32, Dd / 32, 4);
    conv_w_all<<<wgrid, dim3(32, 8)>>>(Wq, Wk, Wv, Wo, wth, wtl);

    cudaFuncSetAttribute(gemm_qkv, cudaFuncAttributeMaxDynamicSharedMemorySize, GEMM_SMEM);
    cudaFuncSetAttribute(gemm_out, cudaFuncAttributeMaxDynamicSharedMemorySize, GEMM_SMEM);

    // 2) Fused QKV projections (one launch, one tail)
    dim3 qkvgrid(Dd / GBN, Mm / GBM, 3);   // (8, 64, 3)
    gemm_qkv<<<qkvgrid, 256, GEMM_SMEM>>>(xh, xl, wth, wtl, bq, bk, bv);

    // 3) Flash attention
    cudaFuncSetAttribute(flash_tc, cudaFuncAttributeMaxDynamicSharedMemorySize, FLASH_SMEM);
    dim3 fgrid(Tt / FBM, Hh, Bq);          // (16, 16, 4)
    flash_tc<<<fgrid, 256, FLASH_SMEM>>>();

    // 4) Output projection (fp32 out)
    dim3 ogrid(Dd / GBN, Mm / GBM);        // (8, 64)
    gemm_out<<<ogrid, 256, GEMM_SMEM>>>(atth, attl, wth + 3 * (size_t)Dd * Dd,
                                        wtl + 3 * (size_t)Dd * Dd, bo, out);
}

// round 13
// speedup vs baseline: 1.0654x; 1.0654x over previous
#include <cuda_runtime.h>
#include <cuda_bf16.h>
#include <math_constants.h>
#include <cstdint>

#define Bq  4
#define Tt  2048
#define Dd  2048
#define Hh  16
#define DHd 128
#define Mm  (Bq * Tt)        // 8192
#define SCALE 0.08838834764831845f  // DH^-0.5

// ---------------------------------------------------------------------------
// Persistent bf16 hi/lo tensors (allocation-free rule: __device__ globals)
// ---------------------------------------------------------------------------
__device__ __align__(256) __nv_bfloat16 g_xh[Mm * Dd];
__device__ __align__(256) __nv_bfloat16 g_xl[Mm * Dd];
__device__ __align__(256) __nv_bfloat16 g_wth[4][Dd * Dd];   // W^T hi, [N][K]
__device__ __align__(256) __nv_bfloat16 g_wtl[4][Dd * Dd];   // W^T lo
__device__ __align__(256) __nv_bfloat16 g_qh[Bq * Hh * Tt * DHd];
__device__ __align__(256) __nv_bfloat16 g_ql[Bq * Hh * Tt * DHd];
__device__ __align__(256) __nv_bfloat16 g_kh[Bq * Hh * Tt * DHd];
__device__ __align__(256) __nv_bfloat16 g_kl[Bq * Hh * Tt * DHd];
__device__ __align__(256) __nv_bfloat16 g_vth[Bq * Hh * DHd * Tt];  // [b,h,d,t]
__device__ __align__(256) __nv_bfloat16 g_vtl[Bq * Hh * DHd * Tt];
__device__ __align__(256) __nv_bfloat16 g_atth[Bq * Tt * Dd];
__device__ __align__(256) __nv_bfloat16 g_attl[Bq * Tt * Dd];

// ===========================================================================
// Helpers
// ===========================================================================
__device__ __forceinline__ uint32_t smem_u32(const void* p) {
    uint32_t a;
    asm("{ .reg .u64 t; cvta.to.shared.u64 t, %1; cvt.u32.u64 %0, t; }" : "=r"(a) : "l"(p));
    return a;
}
__device__ __forceinline__ void cp16(uint32_t dst, const void* src) {
    asm volatile("cp.async.cg.shared.global [%0], [%1], 16;" :: "r"(dst), "l"(src));
}
#define CP_COMMIT() asm volatile("cp.async.commit_group;" ::: "memory")
#define CP_WAIT0()  asm volatile("cp.async.wait_group 0;" ::: "memory")

__device__ __forceinline__ void mma_bf16(float* c, const uint32_t* a,
                                         uint32_t b0, uint32_t b1) {
    asm volatile(
        "mma.sync.aligned.m16n8k16.row.col.f32.bf16.bf16.f32 "
        "{%0,%1,%2,%3}, {%4,%5,%6,%7}, {%8,%9}, {%0,%1,%2,%3};"
        : "+f"(c[0]), "+f"(c[1]), "+f"(c[2]), "+f"(c[3])
        : "r"(a[0]), "r"(a[1]), "r"(a[2]), "r"(a[3]), "r"(b0), "r"(b1));
}
__device__ __forceinline__ void ldsm_x4(uint32_t* r, uint32_t addr) {
    asm volatile("ldmatrix.sync.aligned.m8n8.x4.shared.b16 {%0,%1,%2,%3}, [%4];"
        : "=r"(r[0]), "=r"(r[1]), "=r"(r[2]), "=r"(r[3]) : "r"(addr));
}
__device__ __forceinline__ uint32_t pack_bf16(float v0, float v1) {
    uint32_t h;
    asm("cvt.rn.bf16x2.f32 %0, %1, %2;" : "=r"(h) : "f"(v1), "f"(v0));
    return h;
}
// Split pair of fp32 into bf16x2 hi + bf16x2 residual (lower 16 bits = v0)
__device__ __forceinline__ void bf16_split2(float v0, float v1,
                                            uint32_t& hi, uint32_t& lo) {
    uint32_t h = pack_bf16(v0, v1);
    float f0 = __uint_as_float(h << 16);
    float f1 = __uint_as_float(h & 0xffff0000u);
    lo = pack_bf16(v0 - f0, v1 - f1);
    hi = h;
}

// ===========================================================================
// Conversion kernels
// ===========================================================================
__global__ __launch_bounds__(256)
void conv_x_kernel(const float* __restrict__ src,
                   __nv_bfloat16* __restrict__ hi, __nv_bfloat16* __restrict__ lo)
{
    const size_t i4 = ((size_t)blockIdx.x * 256 + threadIdx.x) * 4;
    float4 v = *(const float4*)(src + i4);
    uint32_t h0, l0, h1, l1;
    bf16_split2(v.x, v.y, h0, l0);
    bf16_split2(v.z, v.w, h1, l1);
    *(uint2*)(hi + i4) = make_uint2(h0, h1);
    *(uint2*)(lo + i4) = make_uint2(l0, l1);
}

// Transpose all 4 W [K][N] -> W^T [N][K], split to bf16 hi/lo. gridDim.z = 4.
__global__ __launch_bounds__(256)
void conv_w_all(const float* __restrict__ W0, const float* __restrict__ W1,
                const float* __restrict__ W2, const float* __restrict__ W3,
                __nv_bfloat16* __restrict__ Th, __nv_bfloat16* __restrict__ Tl)
{
    const int z = blockIdx.z;
    const float* W = (z == 0) ? W0 : (z == 1) ? W1 : (z == 2) ? W2 : W3;
    __nv_bfloat16* th = Th + (size_t)z * Dd * Dd;
    __nv_bfloat16* tl = Tl + (size_t)z * Dd * Dd;

    __shared__ float tile[32][33];
    int x = blockIdx.x * 32 + threadIdx.x;
    int y = blockIdx.y * 32 + threadIdx.y;
#pragma unroll
    for (int j = 0; j < 32; j += 8)
        tile[threadIdx.y + j][threadIdx.x] = W[(size_t)(y + j) * Dd + x];
    __syncthreads();
    int n = blockIdx.x * 32 + threadIdx.y;
    int k = blockIdx.y * 32 + threadIdx.x;
#pragma unroll
    for (int j = 0; j < 32; j += 8) {
        float v = tile[threadIdx.x][threadIdx.y + j];
        __nv_bfloat16 h = __float2bfloat16(v);
        __nv_bfloat16 l = __float2bfloat16(v - __bfloat162float(h));
        th[(size_t)(n + j) * Dd + k] = h;
        tl[(size_t)(n + j) * Dd + k] = l;
    }
}

// ===========================================================================
// bf16 hi/lo tensor-core GEMM core. BM=BN=128, BK=32, 128 threads
// (4 warps, 2x2 grid, warp tile 64x64 = 128 acc regs).
// 2-stage cp.async double buffer (64KB) -> 3 CTAs/SM = 12 warps/SM.
// Dense 64B rows + 16B-chunk XOR swizzle; all fragments via ldmatrix x4.
// ===========================================================================
#define GBM 128
#define GBN 128
#define GBK 32
#define GTHREADS 128
#define TILEB 8192                    // 128 rows * 64B
#define STAGEB (4 * TILEB)            // 32768: Ah|Al|Bh|Bl
#define GEMM_SMEM (2 * STAGEB)        // 65536 -> 3 CTAs/SM

__device__ __forceinline__ void load_stage(uint32_t sdst,
        const __nv_bfloat16* __restrict__ Ah, const __nv_bfloat16* __restrict__ Al,
        const __nv_bfloat16* __restrict__ Bh, const __nv_bfloat16* __restrict__ Bl,
        int m0, int n0, int k0)
{
    const int tid = threadIdx.x;
#pragma unroll
    for (int l = 0; l < 4; l++) {
        int e = tid + GTHREADS * l;          // 0..511
        int r = e >> 2, c = e & 3;
        int cp_ = c ^ ((r >> 1) & 3);
        uint32_t doff = (uint32_t)(r * 64 + cp_ * 16);
        size_t soff = (size_t)(m0 + r) * Dd + k0 + c * 8;
        cp16(sdst + doff, Ah + soff);
        cp16(sdst + TILEB + doff, Al + soff);
    }
#pragma unroll
    for (int l = 0; l < 4; l++) {
        int e = tid + GTHREADS * l;
        int r = e >> 2, c = e & 3;
        int cp_ = c ^ ((r >> 1) & 3);
        uint32_t doff = (uint32_t)(r * 64 + cp_ * 16);
        size_t soff = (size_t)(n0 + r) * Dd + k0 + c * 8;
        cp16(sdst + 2 * TILEB + doff, Bh + soff);
        cp16(sdst + 3 * TILEB + doff, Bl + soff);
    }
}

__device__ __forceinline__ void gemm_mainloop(
        uint32_t sbase,
        const __nv_bfloat16* __restrict__ Ah, const __nv_bfloat16* __restrict__ Al,
        const __nv_bfloat16* __restrict__ Bth, const __nv_bfloat16* __restrict__ Btl,
        int m0, int n0, float acc[4][8][4])
{
    const int lane = threadIdx.x & 31;
    const int wid  = threadIdx.x >> 5;
    const int wm = wid >> 1, wn = wid & 1;
    const int lr = lane & 7, g = lane >> 3;
    const int swz = (lr >> 1) & 3;
    const uint32_t arow = (uint32_t)((wm * 64 + (g & 1) * 8 + lr) * 64);
    const int akh = g >> 1;
    const uint32_t brow = (uint32_t)((wn * 64 + (g >> 1) * 8 + lr) * 64);
    const int bkh = g & 1;

    load_stage(sbase, Ah, Al, Bth, Btl, m0, n0, 0);
    CP_COMMIT();

    const int NITER = Dd / GBK;   // 64
    for (int it = 0; it < NITER; it++) {
        CP_WAIT0();
        __syncthreads();
        const uint32_t Sb = sbase + (uint32_t)((it & 1) * STAGEB);
        if (it + 1 < NITER) {
            load_stage(sbase + (uint32_t)(((it + 1) & 1) * STAGEB),
                       Ah, Al, Bth, Btl, m0, n0, (it + 1) * GBK);
            CP_COMMIT();
        }
#pragma unroll
        for (int ks = 0; ks < 2; ks++) {
            const uint32_t ca = (uint32_t)(((ks * 2 + akh) ^ swz) * 16);
            const uint32_t cb = (uint32_t)(((ks * 2 + bkh) ^ swz) * 16);
            uint32_t ah[4][4], al[4][4];
#pragma unroll
            for (int i = 0; i < 4; i++) {
                ldsm_x4(ah[i], Sb + arow + (uint32_t)(i * 1024) + ca);
                ldsm_x4(al[i], Sb + TILEB + arow + (uint32_t)(i * 1024) + ca);
            }
#pragma unroll
            for (int jj = 0; jj < 4; jj++) {
                uint32_t bh4[4], bl4[4];
                ldsm_x4(bh4, Sb + 2 * TILEB + brow + (uint32_t)(jj * 1024) + cb);
                ldsm_x4(bl4, Sb + 3 * TILEB + brow + (uint32_t)(jj * 1024) + cb);
#pragma unroll
                for (int i = 0; i < 4; i++) {
                    mma_bf16(acc[i][2 * jj], ah[i], bh4[0], bh4[1]);
                    mma_bf16(acc[i][2 * jj], al[i], bh4[0], bh4[1]);
                    mma_bf16(acc[i][2 * jj], ah[i], bl4[0], bl4[1]);
                    mma_bf16(acc[i][2 * jj + 1], ah[i], bh4[2], bh4[3]);
                    mma_bf16(acc[i][2 * jj + 1], al[i], bh4[2], bh4[3]);
                    mma_bf16(acc[i][2 * jj + 1], ah[i], bl4[2], bl4[3]);
                }
            }
        }
    }
}

// Fused QKV projection: gridDim.z selects q/k/v weight + epilogue.
__global__ __launch_bounds__(GTHREADS, 3)
void gemm_qkv(const __nv_bfloat16* __restrict__ xh, const __nv_bfloat16* __restrict__ xl,
              const __nv_bfloat16* __restrict__ wth, const __nv_bfloat16* __restrict__ wtl,
              const float* __restrict__ bq, const float* __restrict__ bk,
              const float* __restrict__ bv)
{
    extern __shared__ char smem[];
    const uint32_t sbase = smem_u32(smem);
    const int z = blockIdx.z;
    const __nv_bfloat16* Bth = wth + (size_t)z * Dd * Dd;
    const __nv_bfloat16* Btl = wtl + (size_t)z * Dd * Dd;
    const float* bias = (z == 0) ? bq : (z == 1) ? bk : bv;
    const int m0 = blockIdx.y * GBM;
    const int n0 = blockIdx.x * GBN;

    float acc[4][8][4];
#pragma unroll
    for (int i = 0; i < 4; i++)
#pragma unroll
        for (int j = 0; j < 8; j++)
#pragma unroll
            for (int r = 0; r < 4; r++) acc[i][j][r] = 0.f;

    gemm_mainloop(sbase, xh, xl, Bth, Btl, m0, n0, acc);

    const int lane = threadIdx.x & 31;
    const int wid  = threadIdx.x >> 5;
    const int q4 = lane & 3, g8 = lane >> 2;
    const int wm = wid >> 1, wn = wid & 1;
    const int mbase = m0 + wm * 64;
#pragma unroll
    for (int j = 0; j < 8; j++) {
        const int nc = wn * 64 + j * 8 + 2 * q4;
        const float bx = bias[n0 + nc];
        const float by = bias[n0 + nc + 1];
#pragma unroll
        for (int i = 0; i < 4; i++) {
#pragma unroll
            for (int half = 0; half < 2; half++) {
                const int m = mbase + i * 16 + g8 + half * 8;
                float vx = acc[i][j][half * 2]     + bx;
                float vy = acc[i][j][half * 2 + 1] + by;
                const int h = n0 >> 7;               // BN=128 = one head
                const int d = nc;
                const int b = m >> 11;
                const int t = m & 2047;
                if (z == 2) {
                    size_t base = ((size_t)(b * Hh + h) * DHd + d) * Tt + t;
                    __nv_bfloat16 h0 = __float2bfloat16(vx);
                    __nv_bfloat16 h1 = __float2bfloat16(vy);
                    g_vth[base]       = h0;
                    g_vth[base + Tt]  = h1;
                    g_vtl[base]       = __float2bfloat16(vx - __bfloat162float(h0));
                    g_vtl[base + Tt]  = __float2bfloat16(vy - __bfloat162float(h1));
                } else {
                    __nv_bfloat16* dh = (z == 0) ? g_qh : g_kh;
                    __nv_bfloat16* dl = (z == 0) ? g_ql : g_kl;
                    size_t base = ((size_t)((b * Hh + h) * Tt) + t) * DHd + d;
                    uint32_t hh, ll;
                    bf16_split2(vx, vy, hh, ll);
                    *(uint32_t*)(dh + base) = hh;
                    *(uint32_t*)(dl + base) = ll;
                }
            }
        }
    }
}

// Output projection: fp32 row-major result.
__global__ __launch_bounds__(GTHREADS, 3)
void gemm_out(const __nv_bfloat16* __restrict__ Ah, const __nv_bfloat16* __restrict__ Al,
              const __nv_bfloat16* __restrict__ Bth, const __nv_bfloat16* __restrict__ Btl,
              const float* __restrict__ bias, float* __restrict__ Cout)
{
    extern __shared__ char smem[];
    const uint32_t sbase = smem_u32(smem);
    const int m0 = blockIdx.y * GBM;
    const int n0 = blockIdx.x * GBN;

    float acc[4][8][4];
#pragma unroll
    for (int i = 0; i < 4; i++)
#pragma unroll
        for (int j = 0; j < 8; j++)
#pragma unroll
            for (int r = 0; r < 4; r++) acc[i][j][r] = 0.f;

    gemm_mainloop(sbase, Ah, Al, Bth, Btl, m0, n0, acc);

    const int lane = threadIdx.x & 31;
    const int wid  = threadIdx.x >> 5;
    const int q4 = lane & 3, g8 = lane >> 2;
    const int wm = wid >> 1, wn = wid & 1;
    const int mbase = m0 + wm * 64;
#pragma unroll
    for (int j = 0; j < 8; j++) {
        const int nc = wn * 64 + j * 8 + 2 * q4;
        const float bx = bias[n0 + nc];
        const float by = bias[n0 + nc + 1];
#pragma unroll
        for (int i = 0; i < 4; i++) {
#pragma unroll
            for (int half = 0; half < 2; half++) {
                const int m = mbase + i * 16 + g8 + half * 8;
                *(float2*)(Cout + (size_t)m * Dd + n0 + nc) =
                    make_float2(acc[i][j][half * 2] + bx, acc[i][j][half * 2 + 1] + by);
            }
        }
    }
}

// ===========================================================================
// Flash attention (causal), bf16 hi/lo, 3-pass MMA, online softmax.
// BM=128 (8 warps x 16 rows), BN=64, DH=128, 256 threads. (unchanged R11)
// ===========================================================================
#define FBM 128
#define FBN 64
#define QP32 68     // u32 pitch (136 bf16, 272B)
#define KP32 68
#define VP32 36     // 72 bf16, 144B
#define PP32 36
#define F_QH   0u
#define F_QL   34816u
#define F_KH   69632u
#define F_KL   87040u
#define F_V0H  104448u
#define F_VLO  18432u      // lo offset within a V buffer
#define F_VSTR 36864u      // stride between V buffers
#define F_PH   178176u
#define F_PL   196608u
#define FLASH_SMEM 215040

__device__ __forceinline__ void flash_load_q(uint32_t sb,
        const __nv_bfloat16* __restrict__ qh, const __nv_bfloat16* __restrict__ ql) {
    const int tid = threadIdx.x;
#pragma unroll
    for (int l = 0; l < 8; l++) {
        int e = tid + l * 256;
        int r = e >> 4, c = e & 15;
        uint32_t doff = (uint32_t)(r * 272 + c * 16);
        cp16(sb + F_QH + doff, qh + r * 128 + c * 8);
        cp16(sb + F_QL + doff, ql + r * 128 + c * 8);
    }
}
__device__ __forceinline__ void flash_load_k(uint32_t sb,
        const __nv_bfloat16* __restrict__ kh, const __nv_bfloat16* __restrict__ kl) {
    const int tid = threadIdx.x;
#pragma unroll
    for (int l = 0; l < 4; l++) {
        int e = tid + l * 256;
        int r = e >> 4, c = e & 15;
        uint32_t doff = (uint32_t)(r * 272 + c * 16);
        cp16(sb + F_KH + doff, kh + r * 128 + c * 8);
        cp16(sb + F_KL + doff, kl + r * 128 + c * 8);
    }
}
__device__ __forceinline__ void flash_load_v(uint32_t dsth,
        const __nv_bfloat16* __restrict__ vh, const __nv_bfloat16* __restrict__ vl) {
    const int tid = threadIdx.x;
#pragma unroll
    for (int l = 0; l < 4; l++) {
        int e = tid + l * 256;
        int r = e >> 3, c = e & 7;
        uint32_t doff = (uint32_t)(r * 144 + c * 16);
        cp16(dsth + doff, vh + (size_t)r * Tt + c * 8);
        cp16(dsth + F_VLO + doff, vl + (size_t)r * Tt + c * 8);
    }
}

__global__ __launch_bounds__(256, 1)
void flash_tc()
{
    extern __shared__ char smc[];
    const uint32_t sb = smem_u32(smc);
    const int qb = (gridDim.x - 1) - blockIdx.x;    // longest-job-first
    const int h  = blockIdx.y;
    const int b  = blockIdx.z;
    const int q0 = qb * FBM;
    const int tid  = threadIdx.x;
    const int w    = tid >> 5;
    const int lane = tid & 31;
    const int q4   = lane & 3;
    const int rl   = lane >> 2;
    const int lr   = lane & 7;
    const int g    = lane >> 3;

    uint32_t* Ph32 = (uint32_t*)(smc + F_PH);
    uint32_t* Pl32 = (uint32_t*)(smc + F_PL);

    const uint32_t qAddr = sb + F_QH + (uint32_t)((w * 16 + (g & 1) * 8 + lr) * 272 + (g >> 1) * 16);
    const uint32_t kAddr = sb + F_KH + (uint32_t)(((g >> 1) * 8 + lr) * 272 + (g & 1) * 16);
    const uint32_t pAddr = sb + F_PH + (uint32_t)((w * 16 + (g & 1) * 8 + lr) * 144 + (g >> 1) * 16);
    const uint32_t vAddrOff = (uint32_t)(((g >> 1) * 8 + lr) * 144 + (g & 1) * 16);

    const size_t bh = (size_t)(b * Hh + h) * Tt;
    const __nv_bfloat16* kbh = g_kh + bh * DHd;
    const __nv_bfloat16* kbl = g_kl + bh * DHd;
    const __nv_bfloat16* vbh = g_vth + (size_t)(b * Hh + h) * DHd * Tt;
    const __nv_bfloat16* vbl = g_vtl + (size_t)(b * Hh + h) * DHd * Tt;

    flash_load_q(sb, g_qh + (bh + q0) * DHd, g_ql + (bh + q0) * DHd);
    flash_load_k(sb, kbh, kbl);
    flash_load_v(sb + F_V0H, vbh, vbl);
    CP_COMMIT();

    float m_lo = -1e30f, m_hi = -1e30f, l_lo = 0.f, l_hi = 0.f;
    float o[16][4];
#pragma unroll
    for (int nt = 0; nt < 16; nt++)
#pragma unroll
        for (int r = 0; r < 4; r++) o[nt][r] = 0.f;

    const int rowbase = q0 + w * 16;
    const int nkt = 2 * qb + 2;

    for (int t = 0; t < nkt; t++) {
        const int k0 = t * FBN;
        const bool active = (k0 <= rowbase + 15);
        CP_WAIT0();
        __syncthreads();

        if (t + 1 < nkt) {
            flash_load_v(sb + F_V0H + (uint32_t)((t + 1) & 1) * F_VSTR,
                         vbh + (size_t)(t + 1) * FBN, vbl + (size_t)(t + 1) * FBN);
            CP_COMMIT();
        }

        float sacc[8][4];
        if (active) {
#pragma unroll
            for (int j = 0; j < 8; j++)
#pragma unroll
                for (int r = 0; r < 4; r++) sacc[j][r] = 0.f;

#pragma unroll
            for (int ks = 0; ks < 8; ks++) {
                uint32_t ah[4], al[4];
                ldsm_x4(ah, qAddr + (uint32_t)(ks * 32));
                ldsm_x4(al, qAddr + (F_QL - F_QH) + (uint32_t)(ks * 32));
#pragma unroll
                for (int jj = 0; jj < 4; jj++) {
                    uint32_t bh4[4], bl4[4];
                    ldsm_x4(bh4, kAddr + (uint32_t)(jj * 16 * 272 + ks * 32));
                    ldsm_x4(bl4, kAddr + (F_KL - F_KH) + (uint32_t)(jj * 16 * 272 + ks * 32));
                    mma_bf16(sacc[2 * jj], ah, bh4[0], bh4[1]);
                    mma_bf16(sacc[2 * jj], al, bh4[0], bh4[1]);
                    mma_bf16(sacc[2 * jj], ah, bl4[0], bl4[1]);
                    mma_bf16(sacc[2 * jj + 1], ah, bh4[2], bh4[3]);
                    mma_bf16(sacc[2 * jj + 1], al, bh4[2], bh4[3]);
                    mma_bf16(sacc[2 * jj + 1], ah, bl4[2], bl4[3]);
                }
            }
        }

        __syncthreads();
        if (t + 1 < nkt) {
            flash_load_k(sb, kbh + (size_t)(t + 1) * FBN * DHd,
                         kbl + (size_t)(t + 1) * FBN * DHd);
            CP_COMMIT();
        }

        if (active) {
            const int R_lo = rowbase + rl;
            const int R_hi = R_lo + 8;
            const bool needmask = (k0 + FBN - 1) > rowbase;
            float tl = -1e30f, th = -1e30f;
#pragma unroll
            for (int j = 0; j < 8; j++) {
#pragma unroll
                for (int r = 0; r < 4; r++) sacc[j][r] *= SCALE;
                if (needmask) {
                    const int C = k0 + j * 8 + 2 * q4;
                    if (C > R_lo)     sacc[j][0] = -1e30f;
                    if (C + 1 > R_lo) sacc[j][1] = -1e30f;
                    if (C > R_hi)     sacc[j][2] = -1e30f;
                    if (C + 1 > R_hi) sacc[j][3] = -1e30f;
                }
                tl = fmaxf(tl, fmaxf(sacc[j][0], sacc[j][1]));
                th = fmaxf(th, fmaxf(sacc[j][2], sacc[j][3]));
            }
            tl = fmaxf(tl, __shfl_xor_sync(0xffffffffu, tl, 1));
            tl = fmaxf(tl, __shfl_xor_sync(0xffffffffu, tl, 2));
            th = fmaxf(th, __shfl_xor_sync(0xffffffffu, th, 1));
            th = fmaxf(th, __shfl_xor_sync(0xffffffffu, th, 2));

            const float mn_lo = fmaxf(m_lo, tl);
            const float mn_hi = fmaxf(m_hi, th);
            const float a_lo = __expf(m_lo - mn_lo);
            const float a_hi = __expf(m_hi - mn_hi);
            m_lo = mn_lo; m_hi = mn_hi;

            float sum_lo = 0.f, sum_hi = 0.f;
            uint32_t* prl_h = Ph32 + (w * 16 + rl) * PP32;
            uint32_t* prl_l = Pl32 + (w * 16 + rl) * PP32;
#pragma unroll
            for (int j = 0; j < 8; j++) {
                float p0 = __expf(sacc[j][0] - mn_lo);
                float p1 = __expf(sacc[j][1] - mn_lo);
                float p2 = __expf(sacc[j][2] - mn_hi);
                float p3 = __expf(sacc[j][3] - mn_hi);
                sum_lo += p0 + p1;
                sum_hi += p2 + p3;
                uint32_t hh, ll;
                bf16_split2(p0, p1, hh, ll);
                prl_h[j * 4 + q4] = hh;
                prl_l[j * 4 + q4] = ll;
                bf16_split2(p2, p3, hh, ll);
                prl_h[8 * PP32 + j * 4 + q4] = hh;
                prl_l[8 * PP32 + j * 4 + q4] = ll;
            }
            sum_lo += __shfl_xor_sync(0xffffffffu, sum_lo, 1);
            sum_lo += __shfl_xor_sync(0xffffffffu, sum_lo, 2);
            sum_hi += __shfl_xor_sync(0xffffffffu, sum_hi, 1);
            sum_hi += __shfl_xor_sync(0xffffffffu, sum_hi, 2);
            l_lo = l_lo * a_lo + sum_lo;
            l_hi = l_hi * a_hi + sum_hi;

#pragma unroll
            for (int nt = 0; nt < 16; nt++) {
                o[nt][0] *= a_lo; o[nt][1] *= a_lo;
                o[nt][2] *= a_hi; o[nt][3] *= a_hi;
            }
            __syncwarp();

            const uint32_t vAddr = sb + F_V0H + (uint32_t)(t & 1) * F_VSTR + vAddrOff;
#pragma unroll
            for (int ks = 0; ks < 4; ks++) {
                uint32_t ph4[4], pl4[4];
                ldsm_x4(ph4, pAddr + (uint32_t)(ks * 32));
                ldsm_x4(pl4, pAddr + (F_PL - F_PH) + (uint32_t)(ks * 32));
#pragma unroll
                for (int ntp = 0; ntp < 8; ntp++) {
                    uint32_t vh4[4], vl4[4];
                    ldsm_x4(vh4, vAddr + (uint32_t)(ntp * 16 * 144 + ks * 32));
                    ldsm_x4(vl4, vAddr + F_VLO + (uint32_t)(ntp * 16 * 144 + ks * 32));
                    mma_bf16(o[2 * ntp], ph4, vh4[0], vh4[1]);
                    mma_bf16(o[2 * ntp], pl4, vh4[0], vh4[1]);
                    mma_bf16(o[2 * ntp], ph4, vl4[0], vl4[1]);
                    mma_bf16(o[2 * ntp + 1], ph4, vh4[2], vh4[3]);
                    mma_bf16(o[2 * ntp + 1], pl4, vh4[2], vh4[3]);
                    mma_bf16(o[2 * ntp + 1], ph4, vl4[2], vl4[3]);
                }
            }
        }
    }

    const float il_lo = 1.f / l_lo;
    const float il_hi = 1.f / l_hi;
    __nv_bfloat16* oh = g_atth + ((size_t)(b * Tt + rowbase)) * Dd + h * DHd;
    __nv_bfloat16* ol = g_attl + ((size_t)(b * Tt + rowbase)) * Dd + h * DHd;
#pragma unroll
    for (int nt = 0; nt < 16; nt++) {
        uint32_t hh, ll;
        size_t idx0 = (size_t)rl * Dd + nt * 8 + 2 * q4;
        bf16_split2(o[nt][0] * il_lo, o[nt][1] * il_lo, hh, ll);
        *(uint32_t*)(oh + idx0) = hh;
        *(uint32_t*)(ol + idx0) = ll;
        size_t idx1 = (size_t)(rl + 8) * Dd + nt * 8 + 2 * q4;
        bf16_split2(o[nt][2] * il_hi, o[nt][3] * il_hi, hh, ll);
        *(uint32_t*)(oh + idx1) = hh;
        *(uint32_t*)(ol + idx1) = ll;
    }
}

// ===========================================================================
extern "C" void kernel_launch(void* const* d_in, const int* in_sizes, int n_in,
                              void* d_out, int out_size)
{
    const float* x  = (const float*)d_in[0];
    const float* Wq = (const float*)d_in[1];
    const float* bq = (const float*)d_in[2];
    const float* Wk = (const float*)d_in[3];
    const float* bk = (const float*)d_in[4];
    const float* Wv = (const float*)d_in[5];
    const float* bv = (const float*)d_in[6];
    const float* Wo = (const float*)d_in[7];
    const float* bo = (const float*)d_in[8];
    float* out = (float*)d_out;

    __nv_bfloat16 *xh, *xl, *wth, *wtl, *atth, *attl;
    cudaGetSymbolAddress((void**)&xh,   g_xh);
    cudaGetSymbolAddress((void**)&xl,   g_xl);
    cudaGetSymbolAddress((void**)&wth,  g_wth);
    cudaGetSymbolAddress((void**)&wtl,  g_wtl);
    cudaGetSymbolAddress((void**)&atth, g_atth);
    cudaGetSymbolAddress((void**)&attl, g_attl);

    // 1) Convert inputs to bf16 hi/lo (x natural, all 4 W transposed, fused)
    conv_x_kernel<<<(Mm * Dd) / 1024, 256>>>(x, xh, xl);
    dim3 wgrid(Dd / 32, Dd / 32, 4);
    conv_w_all<<<wgrid, dim3(32, 8)>>>(Wq, Wk, Wv, Wo, wth, wtl);

    cudaFuncSetAttribute(gemm_qkv, cudaFuncAttributeMaxDynamicSharedMemorySize, GEMM_SMEM);
    cudaFuncSetAttribute(gemm_out, cudaFuncAttributeMaxDynamicSharedMemorySize, GEMM_SMEM);

    // 2) Fused QKV projections (one launch, one tail)
    dim3 qkvgrid(Dd / GBN, Mm / GBM, 3);   // (16, 64, 3)
    gemm_qkv<<<qkvgrid, GTHREADS, GEMM_SMEM>>>(xh, xl, wth, wtl, bq, bk, bv);

    // 3) Flash attention
    cudaFuncSetAttribute(flash_tc, cudaFuncAttributeMaxDynamicSharedMemorySize, FLASH_SMEM);
    dim3 fgrid(Tt / FBM, Hh, Bq);          // (16, 16, 4)
    flash_tc<<<fgrid, 256, FLASH_SMEM>>>();

    // 4) Output projection (fp32 out)
    dim3 ogrid(Dd / GBN, Mm / GBM);        // (16, 64)
    gemm_out<<<ogrid, GTHREADS, GEMM_SMEM>>>(atth, attl, wth + 3 * (size_t)Dd * Dd,
                                             wtl + 3 * (size_t)Dd * Dd, bo, out);
}